// round 17
// baseline (speedup 1.0000x reference)
#include <cuda_runtime.h>
#include <cstdint>
#include <cstddef>
#include <math.h>

#define D_DIM 2048
#define E_DIM 64
#define TM    128
#define KC    64
#define NCH   32          // chunks of K
#define NTHREADS 256
#define TOPK  8
#define PITCH 68          // floats per token row in smem A tile (bank pad)

#define PLANE (TM * PITCH)            // floats per split-plane
#define SMEM_BYTES (4 * PLANE * 4)    // 2 buffers x 2 splits = 139264 B

typedef unsigned long long u64;

// W fragments, fragment-ordered: [S=256][M=4][p=2][lane*4 + r]
__device__ float g_Wf[256 * 4 * 2 * 128];

// ---- prep: split W into tf32 hi/lo, store in mma-fragment order ----
__global__ void prep_W(const float* __restrict__ W) {
    int idx = blockIdx.x * blockDim.x + threadIdx.x;   // 131072
    int e = idx >> 11, k = idx & 2047;
    float a = W[idx];
    float ah = __uint_as_float(__float_as_uint(a) & 0xFFFFE000u);
    float al = a - ah;
    int s = k >> 3, M = e >> 4;
    int l = (e & 7) * 4 + (k & 3);                     // lane
    int r = ((e >> 3) & 1) + 2 * ((k >> 2) & 1);       // frag reg index
    int base = ((s * 4 + M) * 2) * 128 + l * 4 + r;
    g_Wf[base]       = ah;                             // p=0 plane
    g_Wf[base + 128] = al;                             // p=1 plane
}

// tf32 warp MMA: D += A(16x8, experts x k) * B(8x8, k x tokens)
#define MMA(d, a, b)                                                         \
    asm volatile(                                                            \
        "mma.sync.aligned.m16n8k8.row.col.f32.tf32.tf32.f32 "                \
        "{%0,%1,%2,%3}, {%4,%5,%6,%7}, {%8,%9}, {%0,%1,%2,%3};"              \
        : "+f"((d)[0]), "+f"((d)[1]), "+f"((d)[2]), "+f"((d)[3])             \
        : "r"((a).x), "r"((a).y), "r"((a).z), "r"((a).w),                    \
          "r"((b)[0]), "r"((b)[1]))

__global__ __launch_bounds__(NTHREADS, 1)
void router_tc(const float* __restrict__ h,
               const float* __restrict__ cal_scale,
               const float* __restrict__ cal_bias,
               float* __restrict__ out, int T) {
    extern __shared__ float smf[];
    const int tid  = threadIdx.x;
    const int lane = tid & 31;
    const int w    = tid >> 5;
    const int we   = w & 1;        // expert half (experts 32we..32we+31)
    const int wt   = w >> 1;       // token quarter (tokens 32wt..32wt+31)
    const int lg   = lane >> 2;    // mma groupID
    const int lt   = lane & 3;     // mma threadID-in-group
    const int t0   = blockIdx.x * TM;

    // main, compensation, chunk accumulators: [m][n][4]
    float dm[2][4][4], cm[2][4][4], dc[2][4][4];
#pragma unroll
    for (int m = 0; m < 2; m++)
#pragma unroll
        for (int n = 0; n < 4; n++)
#pragma unroll
            for (int r = 0; r < 4; r++) {
                dm[m][n][r] = 0.f; cm[m][n][r] = 0.f; dc[m][n][r] = 0.f;
            }

    // splitter roles: iteration q covers element-quad f = tid + 256q
    float4 av[8];
    auto ldg_chunk = [&](int c) {
#pragma unroll
        for (int q = 0; q < 8; q++) {
            int f = tid + 256 * q;
            int t = f >> 4, cq = f & 15;
            av[q] = *(const float4*)(h + (size_t)(t0 + t) * D_DIM + c * KC + 4 * cq);
        }
    };
    auto sts_chunk = [&](int buf) {
#pragma unroll
        for (int q = 0; q < 8; q++) {
            int f = tid + 256 * q;
            int t = f >> 4, cq = f & 15;
            float4 a = av[q];
            float4 ah, al;
            ah.x = __uint_as_float(__float_as_uint(a.x) & 0xFFFFE000u);
            ah.y = __uint_as_float(__float_as_uint(a.y) & 0xFFFFE000u);
            ah.z = __uint_as_float(__float_as_uint(a.z) & 0xFFFFE000u);
            ah.w = __uint_as_float(__float_as_uint(a.w) & 0xFFFFE000u);
            al.x = a.x - ah.x; al.y = a.y - ah.y;
            al.z = a.z - ah.z; al.w = a.w - ah.w;
            float* p0 = smf + (buf * 2) * PLANE + t * PITCH + 4 * cq;
            *(float4*)p0 = ah;
            *(float4*)(p0 + PLANE) = al;
        }
    };

    ldg_chunk(0);
    sts_chunk(0);
    __syncthreads();

    for (int c = 0; c < NCH; c++) {
        const int buf = c & 1;
        if (c + 1 < NCH) ldg_chunk(c + 1);

        const float* A0 = smf + (buf * 2 + 0) * PLANE;
        const float* A1 = smf + (buf * 2 + 1) * PLANE;

#pragma unroll 2
        for (int st = 0; st < 8; st++) {
            const int S = c * 8 + st;
            // W fragments (coalesced LDG.128, L1-resident)
            uint4 wf[2][2];
#pragma unroll
            for (int m = 0; m < 2; m++)
#pragma unroll
                for (int p = 0; p < 2; p++)
                    wf[m][p] = *(const uint4*)(g_Wf +
                        ((S * 4 + (2 * we + m)) * 2 + p) * 128 + lane * 4);
            // token fragments (conflict-free LDS.32, pitch 68)
            uint32_t tf[2][4][2];
#pragma unroll
            for (int n = 0; n < 4; n++) {
                int off = (32 * wt + 8 * n + lg) * PITCH + 8 * st + lt;
                tf[0][n][0] = __float_as_uint(A0[off]);
                tf[0][n][1] = __float_as_uint(A0[off + 4]);
                tf[1][n][0] = __float_as_uint(A1[off]);
                tf[1][n][1] = __float_as_uint(A1[off + 4]);
            }
            // 24 MMAs: hh + h*l + l*h into chunk accumulators
#pragma unroll
            for (int m = 0; m < 2; m++)
#pragma unroll
                for (int n = 0; n < 4; n++) {
                    MMA(dc[m][n], wf[m][0], tf[0][n]);
                    MMA(dc[m][n], wf[m][0], tf[1][n]);
                    MMA(dc[m][n], wf[m][1], tf[0][n]);
                }
        }
        // Kahan-merge chunk into main, zero chunk
#pragma unroll
        for (int m = 0; m < 2; m++)
#pragma unroll
            for (int n = 0; n < 4; n++)
#pragma unroll
                for (int r = 0; r < 4; r++) {
                    float y = dc[m][n][r];
                    float t = dm[m][n][r] + y;
                    cm[m][n][r] += (dm[m][n][r] - t) + y;
                    dm[m][n][r] = t;
                    dc[m][n][r] = 0.f;
                }

        if (c + 1 < NCH) sts_chunk(buf ^ 1);
        __syncthreads();
    }

    // ---- scatter logits (D[expert][token]) into smem [token][65] ----
    float* L = smf;
#pragma unroll
    for (int m = 0; m < 2; m++)
#pragma unroll
        for (int n = 0; n < 4; n++) {
            int eb = 32 * we + 16 * m + lg;
            int tb = 32 * wt + 8 * n + 2 * lt;
            float v0 = dm[m][n][0] + cm[m][n][0];
            float v1 = dm[m][n][1] + cm[m][n][1];
            float v2 = dm[m][n][2] + cm[m][n][2];
            float v3 = dm[m][n][3] + cm[m][n][3];
            L[(tb + 0) * 65 + eb]     = v0;
            L[(tb + 1) * 65 + eb]     = v1;
            L[(tb + 0) * 65 + eb + 8] = v2;
            L[(tb + 1) * 65 + eb + 8] = v3;
        }
    __syncthreads();

    // ---- per-token: calibrate, softmax, top-8 ----
    if (tid < TM) {
        const int t = tid;
        float* row = L + t * 65;
#pragma unroll 8
        for (int e = 0; e < E_DIM; e++)
            row[e] = fmaf(row[e], cal_scale[e], cal_bias[e]);

        float m = row[0];
#pragma unroll 8
        for (int e = 1; e < E_DIM; e++) m = fmaxf(m, row[e]);
        float ssum = 0.0f;
#pragma unroll 8
        for (int e = 0; e < E_DIM; e++) {
            float p = expf(row[e] - m);
            row[e] = p;
            ssum += p;
        }
        float inv = 1.0f / ssum;
        float* oprob = out + (size_t)(t0 + t) * E_DIM;
#pragma unroll 8
        for (int e = 0; e < E_DIM; e++) {
            float p = row[e] * inv;
            row[e] = p;
            oprob[e] = p;
        }

        const size_t base_w = (size_t)T * E_DIM;
        const size_t base_i = base_w + (size_t)T * TOPK;
        u64 used = 0ULL;
#pragma unroll
        for (int r = 0; r < TOPK; r++) {
            float bv = -1.0f;
            int bi = 0;
            for (int e = 0; e < E_DIM; e++) {
                bool ok = !((used >> e) & 1ULL);
                float p = row[e];
                if (ok && p > bv) { bv = p; bi = e; }
            }
            used |= 1ULL << bi;
            out[base_w + (size_t)(t0 + t) * TOPK + r] = bv;
            out[base_i + (size_t)(t0 + t) * TOPK + r] = (float)bi;
        }
    }
}

extern "C" void kernel_launch(void* const* d_in, const int* in_sizes, int n_in,
                              void* d_out, int out_size) {
    const float* h  = (const float*)d_in[0];
    const float* W  = (const float*)d_in[1];
    const float* cs = (const float*)d_in[2];
    const float* cb = (const float*)d_in[3];
    float* out = (float*)d_out;

    cudaFuncSetAttribute(router_tc, cudaFuncAttributeMaxDynamicSharedMemorySize,
                         SMEM_BYTES);

    int T = in_sizes[0] / D_DIM;       // 16384
    prep_W<<<(E_DIM * D_DIM) / 256, 256>>>(W);
    router_tc<<<T / TM, NTHREADS, SMEM_BYTES>>>(h, cs, cb, out, T);
}